// round 5
// baseline (speedup 1.0000x reference)
#include <cuda_runtime.h>
#include <math.h>
#include <float.h>

#define F_FRAMES 128
#define NPRED    300
#define MTGT     32
#define NCLS     2
#define KID      512

#define HTHREADS 320
#define NWARPS   (HTHREADS/32)
#define KPL      10           // columns per lane: j = lane + 32*k, j in 0..300

__device__ double g_part[F_FRAMES * 3];   // per-frame [l1_sum, giou_sum, nll_sum]

struct XY { float x1, y1, x2, y2, area; };

__device__ __forceinline__ XY to_xyxy(float cx, float cy, float w, float h) {
    XY r;
    r.x1 = cx - 0.5f * w; r.y1 = cy - 0.5f * h;
    r.x2 = cx + 0.5f * w; r.y2 = cy + 0.5f * h;
    r.area = (r.x2 - r.x1) * (r.y2 - r.y1);
    return r;
}

__device__ __forceinline__ float giou_xy(const XY& a, const XY& b) {
    float ltx = fmaxf(a.x1, b.x1), lty = fmaxf(a.y1, b.y1);
    float rbx = fminf(a.x2, b.x2), rby = fminf(a.y2, b.y2);
    float w = fmaxf(rbx - ltx, 0.f), h = fmaxf(rby - lty, 0.f);
    float inter = w * h;
    float uni = a.area + b.area - inter;
    float iou = inter / uni;
    float LTx = fminf(a.x1, b.x1), LTy = fminf(a.y1, b.y1);
    float RBx = fmaxf(a.x2, b.x2), RBy = fmaxf(a.y2, b.y2);
    float W = fmaxf(RBx - LTx, 0.f), H = fmaxf(RBy - LTy, 0.f);
    float ac = W * H;
    return iou - (ac - uni) / ac;
}

// order-preserving map double -> uint64 (smaller double => smaller key)
__device__ __forceinline__ unsigned long long dkey(double d) {
    unsigned long long b = (unsigned long long)__double_as_longlong(d);
    return (b & 0x8000000000000000ULL) ? ~b : (b ^ 0x8000000000000000ULL);
}

// One block per frame: cost build (all warps) -> JV solve (warp 0, warp-sync)
// -> loss epilogue (all warps). Writes per-frame partial sums.
__global__ __launch_bounds__(HTHREADS, 1)
void motip_kernel(const float* __restrict__ pl,   // [F,N,2]
                  const float* __restrict__ pb,   // [F,N,4]
                  const float* __restrict__ il,   // [F,N,512]
                  const int*   __restrict__ tlab, // [F,M]
                  const float* __restrict__ tbx,  // [F,M,4]
                  const int*   __restrict__ tids) // [F,M]
{
    const int f    = blockIdx.x;
    const int tid  = threadIdx.x;
    const int lane = tid & 31;
    const int wid  = tid >> 5;

    __shared__ float  s_cost[MTGT * NPRED];   // [t][j]
    __shared__ double s_v[NPRED + 1];
    __shared__ double s_minv[NPRED + 1];
    __shared__ double s_u[MTGT + 1];
    __shared__ int    s_way[NPRED + 1];
    __shared__ int    s_p[NPRED + 1];
    __shared__ XY     s_tb[MTGT];
    __shared__ int    s_tl[MTGT];
    __shared__ unsigned long long s_key[2];
    __shared__ int    s_match[MTGT];
    __shared__ double s_acc[3];

    // ---- init + load targets ----
    if (tid < MTGT) {
        const float* t = tbx + (size_t)(f * MTGT + tid) * 4;
        s_tb[tid] = to_xyxy(t[0], t[1], t[2], t[3]);
        s_tl[tid] = tlab[f * MTGT + tid];
    }
    if (tid <= NPRED) { s_v[tid] = 0.0; s_p[tid] = 0; }
    if (tid <= MTGT)  s_u[tid] = 0.0;
    if (tid < 3)      s_acc[tid] = 0.0;
    __syncthreads();

    // ---- cost build: thread j handles pred j ----
    if (tid < NPRED) {
        const float* lg = pl + (size_t)(f * NPRED + tid) * NCLS;
        float x0 = lg[0], x1 = lg[1];
        float mx = fmaxf(x0, x1);
        float e0 = expf(x0 - mx), e1 = expf(x1 - mx);
        float inv = 1.0f / (e0 + e1);
        float prob[2] = { e0 * inv, e1 * inv };

        const float* bp = pb + (size_t)(f * NPRED + tid) * 4;
        float cx = bp[0], cy = bp[1], bw = bp[2], bh = bp[3];
        XY a = to_xyxy(cx, cy, bw, bh);

        #pragma unroll 4
        for (int t = 0; t < MTGT; t++) {
            const float* tb4 = tbx + (size_t)(f * MTGT + t) * 4;
            float l1 = fabsf(cx - tb4[0]) + fabsf(cy - tb4[1])
                     + fabsf(bw - tb4[2]) + fabsf(bh - tb4[3]);
            float g  = giou_xy(a, s_tb[t]);
            float cc = -prob[s_tl[t]];
            s_cost[t * NPRED + tid] = 2.0f * cc + 5.0f * l1 + 2.0f * (-g);
        }
    }
    __syncthreads();

    // ---- JV solve: warp 0 only, warp-synchronous ----
    if (wid == 0) {
        for (int i = 1; i <= MTGT; i++) {
            // phase reset
            #pragma unroll
            for (int k = 0; k < KPL; k++) {
                int j = lane + 32 * k;
                if (j <= NPRED) s_minv[j] = DBL_MAX;
            }
            unsigned usedm = 0;
            if (lane == 0) {
                usedm = 1u;                 // virtual column 0 used
                s_p[0] = i;
                s_key[0] = 0xFFFFFFFFFFFFFFFFULL;
                s_key[1] = 0xFFFFFFFFFFFFFFFFULL;
            }
            int j0 = 0;
            int par = 0;
            __syncwarp();

            while (true) {
                const int    i0   = s_p[j0];
                const double u_i0 = s_u[i0];
                const float* crow = &s_cost[(i0 - 1) * NPRED];

                unsigned long long bk = 0xFFFFFFFFFFFFFFFFULL;
                #pragma unroll
                for (int k = 0; k < KPL; k++) {
                    int j = lane + 32 * k;
                    if (j >= 1 && j <= NPRED && !((usedm >> k) & 1u)) {
                        double mv  = s_minv[j];
                        double cur = (double)crow[j - 1] - u_i0 - s_v[j];
                        if (cur < mv) { mv = cur; s_minv[j] = cur; s_way[j] = j0; }
                        unsigned long long key =
                            (dkey(mv) & ~511ULL) | (unsigned long long)j;
                        bk = min(bk, key);
                    }
                }
                atomicMin(&s_key[par], bk);
                __syncwarp();

                const unsigned long long kk = s_key[par];
                const int    j1    = (int)(kk & 511ULL);
                const double delta = s_minv[j1];
                const int    pj1   = s_p[j1];
                if (lane == 0) s_key[par ^ 1] = 0xFFFFFFFFFFFFFFFFULL;
                __syncwarp();

                // potential / minv update (uses pre-j1 usedm, matching reference)
                #pragma unroll
                for (int k = 0; k < KPL; k++) {
                    int j = lane + 32 * k;
                    if (j <= NPRED) {
                        if ((usedm >> k) & 1u) {
                            s_u[s_p[j]] += delta;   // distinct rows -> no conflict
                            s_v[j]      -= delta;
                        } else if (j >= 1) {
                            s_minv[j]   -= delta;
                        }
                    }
                }
                // mark j1 used (owner lane)
                if (lane == (j1 & 31)) usedm |= 1u << (j1 >> 5);
                __syncwarp();

                par ^= 1;        // FIX: reduce into the freshly reset slot next iter
                j0 = j1;
                if (pj1 == 0) break;
            }

            // augment (scalar, lane 0)
            if (lane == 0) {
                int jj = j0;
                while (jj) {
                    int jn = s_way[jj];
                    s_p[jj] = s_p[jn];
                    jj = jn;
                }
            }
            __syncwarp();
        }
    }
    __syncthreads();

    // ---- emit matches to smem ----
    if (tid < NPRED) {
        const int j = tid + 1;
        const int r = s_p[j];
        if (r > 0) s_match[r - 1] = j - 1;
    }
    __syncthreads();

    // ---- L1 + pair GIoU: one thread per target ----
    if (tid < MTGT) {
        const int idx = s_match[tid];
        const float* bp2 = pb  + (size_t)(f * NPRED + idx) * 4;
        const float* bt  = tbx + (size_t)(f * MTGT + tid) * 4;
        float l1 = fabsf(bp2[0] - bt[0]) + fabsf(bp2[1] - bt[1])
                 + fabsf(bp2[2] - bt[2]) + fabsf(bp2[3] - bt[3]);
        XY a = to_xyxy(bp2[0], bp2[1], bp2[2], bp2[3]);
        XY b = to_xyxy(bt[0], bt[1], bt[2], bt[3]);
        float g = giou_xy(a, b);
        atomicAdd(&s_acc[0], (double)l1);
        atomicAdd(&s_acc[1], (double)g);
    }

    // ---- ID cross-entropy: each warp handles ~3-4 rows of K=512 ----
    double id_part = 0.0;
    for (int t = wid; t < MTGT; t += NWARPS) {
        const int idx = s_match[t];
        const float* row = il + (size_t)(f * NPRED + idx) * KID;
        float xv[16];
        float mx = -FLT_MAX;
        #pragma unroll
        for (int k = 0; k < 16; k++) {
            xv[k] = row[lane + 32 * k];
            mx = fmaxf(mx, xv[k]);
        }
        #pragma unroll
        for (int off = 16; off > 0; off >>= 1)
            mx = fmaxf(mx, __shfl_xor_sync(0xffffffffu, mx, off));
        float se = 0.f;
        #pragma unroll
        for (int k = 0; k < 16; k++) se += __expf(xv[k] - mx);
        #pragma unroll
        for (int off = 16; off > 0; off >>= 1)
            se += __shfl_xor_sync(0xffffffffu, se, off);
        if (lane == 0) {
            float lse = logf(se) + mx;
            int tg = tids[f * MTGT + t];
            id_part += (double)(lse - row[tg]);
        }
    }
    if (lane == 0 && id_part != 0.0) atomicAdd(&s_acc[2], id_part);
    __syncthreads();

    if (tid == 0) {
        g_part[f * 3 + 0] = s_acc[0];
        g_part[f * 3 + 1] = s_acc[1];
        g_part[f * 3 + 2] = s_acc[2];
    }
}

__global__ __launch_bounds__(128)
void finalize_kernel(float* __restrict__ out) {
    const int tid  = threadIdx.x;
    const int lane = tid & 31;
    const int wid  = tid >> 5;

    double a0 = g_part[tid * 3 + 0];
    double a1 = g_part[tid * 3 + 1];
    double a2 = g_part[tid * 3 + 2];

    #pragma unroll
    for (int off = 16; off > 0; off >>= 1) {
        a0 += __shfl_down_sync(0xffffffffu, a0, off);
        a1 += __shfl_down_sync(0xffffffffu, a1, off);
        a2 += __shfl_down_sync(0xffffffffu, a2, off);
    }
    __shared__ double s0[4], s1[4], s2[4];
    if (lane == 0) { s0[wid] = a0; s1[wid] = a1; s2[wid] = a2; }
    __syncthreads();
    if (tid == 0) {
        double t0 = s0[0] + s0[1] + s0[2] + s0[3];
        double t1 = s1[0] + s1[1] + s1[2] + s1[3];
        double t2 = s2[0] + s2[1] + s2[2] + s2[3];
        const double FM = (double)(F_FRAMES * MTGT);
        double l1   = t0 / (FM * 4.0);
        double giou = 1.0 - t1 / FM;
        double idl  = t2 / FM;
        double loss = 5.0 * l1 + 2.0 * giou + 1.0 * idl;
        out[0] = (float)loss;
        out[1] = 0.0f;
        out[2] = (float)l1;
        out[3] = (float)giou;
        out[4] = (float)idl;
    }
}

extern "C" void kernel_launch(void* const* d_in, const int* in_sizes, int n_in,
                              void* d_out, int out_size) {
    const float* pred_logits   = (const float*)d_in[0];  // [8,16,300,2]
    const float* pred_boxes    = (const float*)d_in[1];  // [8,16,300,4]
    const float* id_logits     = (const float*)d_in[2];  // [8,16,300,512]
    const int*   target_labels = (const int*)  d_in[3];  // [128,32]
    const float* target_boxes  = (const float*)d_in[4];  // [128,32,4]
    const int*   target_ids    = (const int*)  d_in[5];  // [128,32]
    float* out = (float*)d_out;

    motip_kernel<<<F_FRAMES, HTHREADS>>>(pred_logits, pred_boxes, id_logits,
                                         target_labels, target_boxes, target_ids);
    finalize_kernel<<<1, 128>>>(out);
}

// round 7
// speedup vs baseline: 2.1173x; 2.1173x over previous
#include <cuda_runtime.h>
#include <math.h>
#include <float.h>

#define F_FRAMES 128
#define NPRED    300
#define MTGT     32
#define NCLS     2
#define KID      512

#define HTHREADS 320
#define NWARPS   (HTHREADS/32)

__device__ double g_part[F_FRAMES * 3];   // per-frame [l1_sum, giou_sum, nll_sum]

struct XY { float x1, y1, x2, y2, area; };

__device__ __forceinline__ XY to_xyxy(float cx, float cy, float w, float h) {
    XY r;
    r.x1 = cx - 0.5f * w; r.y1 = cy - 0.5f * h;
    r.x2 = cx + 0.5f * w; r.y2 = cy + 0.5f * h;
    r.area = (r.x2 - r.x1) * (r.y2 - r.y1);
    return r;
}

__device__ __forceinline__ float giou_xy(const XY& a, const XY& b) {
    float ltx = fmaxf(a.x1, b.x1), lty = fmaxf(a.y1, b.y1);
    float rbx = fminf(a.x2, b.x2), rby = fminf(a.y2, b.y2);
    float w = fmaxf(rbx - ltx, 0.f), h = fmaxf(rby - lty, 0.f);
    float inter = w * h;
    float uni = a.area + b.area - inter;
    float iou = inter / uni;
    float LTx = fminf(a.x1, b.x1), LTy = fminf(a.y1, b.y1);
    float RBx = fmaxf(a.x2, b.x2), RBy = fmaxf(a.y2, b.y2);
    float W = fmaxf(RBx - LTx, 0.f), H = fmaxf(RBy - LTy, 0.f);
    float ac = W * H;
    return iou - (ac - uni) / ac;
}

// order-preserving map double -> uint64 (smaller double => smaller key)
__device__ __forceinline__ unsigned long long dkey(double d) {
    unsigned long long b = (unsigned long long)__double_as_longlong(d);
    return (b & 0x8000000000000000ULL) ? ~b : (b ^ 0x8000000000000000ULL);
}

// One block per frame: cost build -> block-parallel JV (register column state,
// packed-key argmin, 2 barriers/iter) -> loss epilogue.
__global__ __launch_bounds__(HTHREADS, 1)
void motip_kernel(const float* __restrict__ pl,   // [F,N,2]
                  const float* __restrict__ pb,   // [F,N,4]
                  const float* __restrict__ il,   // [F,N,512]
                  const int*   __restrict__ tlab, // [F,M]
                  const float* __restrict__ tbx,  // [F,M,4]
                  const int*   __restrict__ tids) // [F,M]
{
    const int f    = blockIdx.x;
    const int tid  = threadIdx.x;
    const int lane = tid & 31;

    __shared__ float  s_cost[MTGT * NPRED];   // [t][j]
    __shared__ double s_minv[NPRED + 1];      // mirror of register mv (exact delta)
    __shared__ double s_u[MTGT + 1];
    __shared__ int    s_way[NPRED + 1];
    __shared__ int    s_p[NPRED + 1];
    __shared__ XY     s_tb[MTGT];
    __shared__ int    s_tl[MTGT];
    __shared__ unsigned long long s_key[2];
    __shared__ int    s_match[MTGT];
    __shared__ double s_acc[3];

    // ---- init + load targets ----
    if (tid < MTGT) {
        const float* t = tbx + (size_t)(f * MTGT + tid) * 4;
        s_tb[tid] = to_xyxy(t[0], t[1], t[2], t[3]);
        s_tl[tid] = tlab[f * MTGT + tid];
    }
    if (tid <= NPRED) s_p[tid] = 0;
    if (tid <= MTGT)  s_u[tid] = 0.0;
    if (tid < 3)      s_acc[tid] = 0.0;
    __syncthreads();

    // ---- cost build: thread j handles pred j ----
    if (tid < NPRED) {
        const float* lg = pl + (size_t)(f * NPRED + tid) * NCLS;
        float x0 = lg[0], x1 = lg[1];
        float mx = fmaxf(x0, x1);
        float e0 = expf(x0 - mx), e1 = expf(x1 - mx);
        float inv = 1.0f / (e0 + e1);
        float prob[2] = { e0 * inv, e1 * inv };

        const float* bp = pb + (size_t)(f * NPRED + tid) * 4;
        float cx = bp[0], cy = bp[1], bw = bp[2], bh = bp[3];
        XY a = to_xyxy(cx, cy, bw, bh);

        #pragma unroll 4
        for (int t = 0; t < MTGT; t++) {
            const float* tb4 = tbx + (size_t)(f * MTGT + t) * 4;
            float l1 = fabsf(cx - tb4[0]) + fabsf(cy - tb4[1])
                     + fabsf(bw - tb4[2]) + fabsf(bh - tb4[3]);
            float g  = giou_xy(a, s_tb[t]);
            float cc = -prob[s_tl[t]];
            s_cost[t * NPRED + tid] = 2.0f * cc + 5.0f * l1 + 2.0f * (-g);
        }
    }

    // ---- JV solve: all 320 threads; thread tid owns column jcol = tid+1 ----
    const int  jcol   = tid + 1;
    const bool active = (tid < NPRED);
    double v = 0.0;                       // v[jcol] in register

    for (int i = 1; i <= MTGT; i++) {
        double mv   = DBL_MAX;            // minv[jcol] in register
        bool   used = false;
        if (tid == 0) {
            s_p[0]   = i;
            s_key[0] = 0xFFFFFFFFFFFFFFFFULL;
            s_key[1] = 0xFFFFFFFFFFFFFFFFULL;
        }
        int j0  = 0;
        int par = 0;
        __syncthreads();   // phase start (covers cost build on i==1, augment on i>1)

        while (true) {
            const int    i0   = s_p[j0];       // stable during path loop
            const double u_i0 = s_u[i0];

            unsigned long long bk = 0xFFFFFFFFFFFFFFFFULL;
            if (active && !used) {
                double cur = (double)s_cost[(i0 - 1) * NPRED + tid] - u_i0 - v;
                if (cur < mv) {
                    mv = cur;
                    s_minv[jcol] = cur;
                    s_way[jcol]  = j0;
                }
                bk = (dkey(mv) & ~511ULL) | (unsigned long long)jcol;
            }
            // warp butterfly min on packed key
            #pragma unroll
            for (int off = 16; off > 0; off >>= 1)
                bk = min(bk, __shfl_xor_sync(0xffffffffu, bk, off));
            if (lane == 0) atomicMin(&s_key[par], bk);
            __syncthreads();   // barrier A: keys + minv/way stores visible

            const unsigned long long kk = s_key[par];
            const int    j1    = (int)(kk & 511ULL);
            const double delta = s_minv[j1];   // exact fp64
            const int    pj1   = s_p[j1];
            if (tid == 0) {
                s_key[par ^ 1] = 0xFFFFFFFFFFFFFFFFULL;
                s_u[s_p[0]] += delta;          // virtual column 0 (v[0] never read)
            }

            if (active) {
                if (used) {
                    v -= delta;
                    s_u[s_p[jcol]] += delta;   // distinct rows -> no write conflict
                } else {
                    mv -= delta;
                    s_minv[jcol] = mv;
                    if (jcol == j1) used = true;
                }
            }

            par ^= 1;
            j0 = j1;
            __syncthreads();   // barrier B: u/minv updates visible to next compute
            if (pj1 == 0) break;
        }

        // augment (scalar)
        if (tid == 0) {
            int jj = j0;
            while (jj) {
                int jn = s_way[jj];
                s_p[jj] = s_p[jn];
                jj = jn;
            }
        }
        // visibility of s_p covered by next phase's start barrier
    }
    __syncthreads();

    // ---- emit matches to smem ----
    if (active) {
        const int r = s_p[jcol];
        if (r > 0) s_match[r - 1] = jcol - 1;
    }
    __syncthreads();

    // ---- L1 + pair GIoU: one thread per target ----
    if (tid < MTGT) {
        const int idx = s_match[tid];
        const float* bp2 = pb  + (size_t)(f * NPRED + idx) * 4;
        const float* bt  = tbx + (size_t)(f * MTGT + tid) * 4;
        float l1 = fabsf(bp2[0] - bt[0]) + fabsf(bp2[1] - bt[1])
                 + fabsf(bp2[2] - bt[2]) + fabsf(bp2[3] - bt[3]);
        XY a = to_xyxy(bp2[0], bp2[1], bp2[2], bp2[3]);
        XY b = to_xyxy(bt[0], bt[1], bt[2], bt[3]);
        float g = giou_xy(a, b);
        atomicAdd(&s_acc[0], (double)l1);
        atomicAdd(&s_acc[1], (double)g);
    }

    // ---- ID cross-entropy: each warp handles ~3-4 rows of K=512 ----
    const int wid = tid >> 5;
    double id_part = 0.0;
    for (int t = wid; t < MTGT; t += NWARPS) {
        const int idx = s_match[t];
        const float* row = il + (size_t)(f * NPRED + idx) * KID;
        float xv[16];
        float mx = -FLT_MAX;
        #pragma unroll
        for (int k = 0; k < 16; k++) {
            xv[k] = row[lane + 32 * k];
            mx = fmaxf(mx, xv[k]);
        }
        #pragma unroll
        for (int off = 16; off > 0; off >>= 1)
            mx = fmaxf(mx, __shfl_xor_sync(0xffffffffu, mx, off));
        float se = 0.f;
        #pragma unroll
        for (int k = 0; k < 16; k++) se += __expf(xv[k] - mx);
        #pragma unroll
        for (int off = 16; off > 0; off >>= 1)
            se += __shfl_xor_sync(0xffffffffu, se, off);
        if (lane == 0) {
            float lse = logf(se) + mx;
            int tg = tids[f * MTGT + t];
            id_part += (double)(lse - row[tg]);
        }
    }
    if (lane == 0 && id_part != 0.0) atomicAdd(&s_acc[2], id_part);
    __syncthreads();

    if (tid == 0) {
        g_part[f * 3 + 0] = s_acc[0];
        g_part[f * 3 + 1] = s_acc[1];
        g_part[f * 3 + 2] = s_acc[2];
    }
}

__global__ __launch_bounds__(128)
void finalize_kernel(float* __restrict__ out) {
    const int tid  = threadIdx.x;
    const int lane = tid & 31;
    const int wid  = tid >> 5;

    double a0 = g_part[tid * 3 + 0];
    double a1 = g_part[tid * 3 + 1];
    double a2 = g_part[tid * 3 + 2];

    #pragma unroll
    for (int off = 16; off > 0; off >>= 1) {
        a0 += __shfl_down_sync(0xffffffffu, a0, off);
        a1 += __shfl_down_sync(0xffffffffu, a1, off);
        a2 += __shfl_down_sync(0xffffffffu, a2, off);
    }
    __shared__ double s0[4], s1[4], s2[4];
    if (lane == 0) { s0[wid] = a0; s1[wid] = a1; s2[wid] = a2; }
    __syncthreads();
    if (tid == 0) {
        double t0 = s0[0] + s0[1] + s0[2] + s0[3];
        double t1 = s1[0] + s1[1] + s1[2] + s1[3];
        double t2 = s2[0] + s2[1] + s2[2] + s2[3];
        const double FM = (double)(F_FRAMES * MTGT);
        double l1   = t0 / (FM * 4.0);
        double giou = 1.0 - t1 / FM;
        double idl  = t2 / FM;
        double loss = 5.0 * l1 + 2.0 * giou + 1.0 * idl;
        out[0] = (float)loss;
        out[1] = 0.0f;
        out[2] = (float)l1;
        out[3] = (float)giou;
        out[4] = (float)idl;
    }
}

extern "C" void kernel_launch(void* const* d_in, const int* in_sizes, int n_in,
                              void* d_out, int out_size) {
    const float* pred_logits   = (const float*)d_in[0];  // [8,16,300,2]
    const float* pred_boxes    = (const float*)d_in[1];  // [8,16,300,4]
    const float* id_logits     = (const float*)d_in[2];  // [8,16,300,512]
    const int*   target_labels = (const int*)  d_in[3];  // [128,32]
    const float* target_boxes  = (const float*)d_in[4];  // [128,32,4]
    const int*   target_ids    = (const int*)  d_in[5];  // [128,32]
    float* out = (float*)d_out;

    motip_kernel<<<F_FRAMES, HTHREADS>>>(pred_logits, pred_boxes, id_logits,
                                         target_labels, target_boxes, target_ids);
    finalize_kernel<<<1, 128>>>(out);
}

// round 10
// speedup vs baseline: 3.0696x; 1.4498x over previous
#include <cuda_runtime.h>
#include <math.h>
#include <float.h>

#define F_FRAMES 128
#define NPRED    300
#define MTGT     32
#define NCLS     2
#define KID      512

#define HTHREADS 320
#define NWARPS   (HTHREADS/32)

__device__ double   g_part[F_FRAMES * 3];  // per-frame [l1_sum, giou_sum, nll_sum]
__device__ unsigned g_done = 0;            // self-resetting completion counter

struct XY { float x1, y1, x2, y2, area; };

__device__ __forceinline__ XY to_xyxy(float cx, float cy, float w, float h) {
    XY r;
    r.x1 = cx - 0.5f * w; r.y1 = cy - 0.5f * h;
    r.x2 = cx + 0.5f * w; r.y2 = cy + 0.5f * h;
    r.area = (r.x2 - r.x1) * (r.y2 - r.y1);
    return r;
}

__device__ __forceinline__ float giou_xy(const XY& a, const XY& b) {
    float ltx = fmaxf(a.x1, b.x1), lty = fmaxf(a.y1, b.y1);
    float rbx = fminf(a.x2, b.x2), rby = fminf(a.y2, b.y2);
    float w = fmaxf(rbx - ltx, 0.f), h = fmaxf(rby - lty, 0.f);
    float inter = w * h;
    float uni = a.area + b.area - inter;
    float iou = inter / uni;
    float LTx = fminf(a.x1, b.x1), LTy = fminf(a.y1, b.y1);
    float RBx = fmaxf(a.x2, b.x2), RBy = fmaxf(a.y2, b.y2);
    float W = fmaxf(RBx - LTx, 0.f), H = fmaxf(RBy - LTy, 0.f);
    float ac = W * H;
    return iou - (ac - uni) / ac;
}

// order-preserving double -> u64
__device__ __forceinline__ unsigned long long dkey(double d) {
    unsigned long long b = (unsigned long long)__double_as_longlong(d);
    return (b & 0x8000000000000000ULL) ? ~b : (b ^ 0x8000000000000000ULL);
}
// order-preserving float -> u32
__device__ __forceinline__ unsigned f2key(float f) {
    unsigned b = __float_as_uint(f);
    return (b & 0x80000000u) ? ~b : (b | 0x80000000u);
}
__device__ __forceinline__ float key2f(unsigned k) {
    unsigned b = (k & 0x80000000u) ? (k ^ 0x80000000u) : ~k;
    return __uint_as_float(b);
}

__global__ __launch_bounds__(HTHREADS, 1)
void motip_kernel(const float* __restrict__ pl,   // [F,N,2]
                  const float* __restrict__ pb,   // [F,N,4]
                  const float* __restrict__ il,   // [F,N,512]
                  const int*   __restrict__ tlab, // [F,M]
                  const float* __restrict__ tbx,  // [F,M,4]
                  const int*   __restrict__ tids, // [F,M]
                  float* __restrict__ out)        // [5]
{
    const int f    = blockIdx.x;
    const int tid  = threadIdx.x;
    const int lane = tid & 31;
    const int wid  = tid >> 5;

    __shared__ float  s_cost[MTGT * NPRED];   // [t][j]
    __shared__ double s_minv[NPRED + 1];
    __shared__ double s_u[MTGT + 1];
    __shared__ int    s_way[NPRED + 1];
    __shared__ int    s_p[NPRED + 1];
    __shared__ XY     s_tb[MTGT];
    __shared__ int    s_tl[MTGT];
    __shared__ unsigned long long s_key[2];
    __shared__ unsigned long long s_rowkey[MTGT];
    __shared__ int    s_freelist[MTGT];
    __shared__ int    s_nfree;
    __shared__ int    s_match[MTGT];
    __shared__ double s_acc[3];
    __shared__ int    s_islast;

    // ---- init + load targets ----
    if (tid < MTGT) {
        const float* t = tbx + (size_t)(f * MTGT + tid) * 4;
        s_tb[tid] = to_xyxy(t[0], t[1], t[2], t[3]);
        s_tl[tid] = tlab[f * MTGT + tid];
    }
    if (tid <= NPRED) s_p[tid] = 0;
    if (tid < 3)      s_acc[tid] = 0.0;
    __syncthreads();

    // ---- cost build: thread j handles pred j ----
    if (tid < NPRED) {
        const float* lg = pl + (size_t)(f * NPRED + tid) * NCLS;
        float x0 = lg[0], x1 = lg[1];
        float mx = fmaxf(x0, x1);
        float e0 = expf(x0 - mx), e1 = expf(x1 - mx);
        float inv = 1.0f / (e0 + e1);
        float prob[2] = { e0 * inv, e1 * inv };

        const float* bp = pb + (size_t)(f * NPRED + tid) * 4;
        float cx = bp[0], cy = bp[1], bw = bp[2], bh = bp[3];
        XY a = to_xyxy(cx, cy, bw, bh);

        #pragma unroll 4
        for (int t = 0; t < MTGT; t++) {
            const float* tb4 = tbx + (size_t)(f * MTGT + t) * 4;
            float l1 = fabsf(cx - tb4[0]) + fabsf(cy - tb4[1])
                     + fabsf(bw - tb4[2]) + fabsf(bh - tb4[3]);
            float g  = giou_xy(a, s_tb[t]);
            float cc = -prob[s_tl[t]];
            s_cost[t * NPRED + tid] = 2.0f * cc + 5.0f * l1 + 2.0f * (-g);
        }
    }
    __syncthreads();

    // ---- row minima: warp w handles rows w, w+10, ... ----
    for (int r = wid; r < MTGT; r += NWARPS) {
        unsigned long long best = 0xFFFFFFFFFFFFFFFFULL;
        #pragma unroll
        for (int k = 0; k < 10; k++) {
            int j = lane + 32 * k;
            if (j < NPRED) {
                unsigned long long key =
                    ((unsigned long long)f2key(s_cost[r * NPRED + j]) << 32)
                    | (unsigned)j;
                best = min(best, key);
            }
        }
        #pragma unroll
        for (int off = 16; off > 0; off >>= 1)
            best = min(best, __shfl_xor_sync(0xffffffffu, best, off));
        if (lane == 0) s_rowkey[r] = best;
    }
    __syncthreads();

    // ---- greedy tight assignment + dual init (tid 0, serial over 32 rows) ----
    if (tid == 0) {
        int nf = 0;
        s_u[0] = 0.0;
        for (int r = 0; r < MTGT; r++) {
            unsigned long long key = s_rowkey[r];
            int   jmin = (int)(key & 0xFFFFFFFFULL);
            float vmin = key2f((unsigned)(key >> 32));
            s_u[r + 1] = (double)vmin;            // u[i] = exact row min, v = 0
            if (s_p[jmin + 1] == 0) s_p[jmin + 1] = r + 1;   // tight edge, free col
            else                    s_freelist[nf++] = r + 1;
        }
        s_nfree = nf;
    }
    __syncthreads();

    // ---- JV augmentation for conflicted rows only ----
    const int  jcol   = tid + 1;
    const bool active = (tid < NPRED);
    double v = 0.0;                        // v[jcol] in register (greedy leaves v=0)
    const int nfree = s_nfree;

    for (int fi = 0; fi < nfree; fi++) {
        const int i = s_freelist[fi];
        double mv   = DBL_MAX;
        bool   used = false;
        if (tid == 0) {
            s_p[0]   = i;
            s_key[0] = 0xFFFFFFFFFFFFFFFFULL;
            s_key[1] = 0xFFFFFFFFFFFFFFFFULL;
        }
        int j0  = 0;
        int par = 0;
        __syncthreads();   // phase start (covers greedy init / previous augment)

        while (true) {
            const int    i0   = s_p[j0];        // stable during path loop
            const double u_i0 = s_u[i0];

            unsigned long long bk = 0xFFFFFFFFFFFFFFFFULL;
            if (active && !used) {
                double cur = (double)s_cost[(i0 - 1) * NPRED + tid] - u_i0 - v;
                if (cur < mv) {
                    mv = cur;
                    s_minv[jcol] = cur;
                    s_way[jcol]  = j0;
                }
                bk = (dkey(mv) & ~511ULL) | (unsigned long long)jcol;
            }
            #pragma unroll
            for (int off = 16; off > 0; off >>= 1)
                bk = min(bk, __shfl_xor_sync(0xffffffffu, bk, off));
            if (lane == 0) atomicMin(&s_key[par], bk);
            __syncthreads();   // barrier A

            const unsigned long long kk = s_key[par];
            const int    j1    = (int)(kk & 511ULL);
            const double delta = s_minv[j1];    // exact fp64
            const int    pj1   = s_p[j1];
            if (tid == 0) {
                s_key[par ^ 1] = 0xFFFFFFFFFFFFFFFFULL;
                s_u[s_p[0]] += delta;           // virtual column 0
            }

            if (active) {
                if (used) {
                    v -= delta;
                    s_u[s_p[jcol]] += delta;    // distinct rows -> no conflict
                } else {
                    mv -= delta;
                    s_minv[jcol] = mv;
                    if (jcol == j1) used = true;
                }
            }

            par ^= 1;
            j0 = j1;
            __syncthreads();   // barrier B
            if (pj1 == 0) break;
        }

        // augment (scalar)
        if (tid == 0) {
            int jj = j0;
            while (jj) {
                int jn = s_way[jj];
                s_p[jj] = s_p[jn];
                jj = jn;
            }
        }
        // s_p visibility covered by next phase's start barrier
    }
    __syncthreads();

    // ---- emit matches to smem ----
    if (active) {
        const int r = s_p[jcol];
        if (r > 0) s_match[r - 1] = jcol - 1;
    }
    __syncthreads();

    // ---- L1 + pair GIoU: one thread per target ----
    if (tid < MTGT) {
        const int idx = s_match[tid];
        const float* bp2 = pb  + (size_t)(f * NPRED + idx) * 4;
        const float* bt  = tbx + (size_t)(f * MTGT + tid) * 4;
        float l1 = fabsf(bp2[0] - bt[0]) + fabsf(bp2[1] - bt[1])
                 + fabsf(bp2[2] - bt[2]) + fabsf(bp2[3] - bt[3]);
        XY a = to_xyxy(bp2[0], bp2[1], bp2[2], bp2[3]);
        XY b = to_xyxy(bt[0], bt[1], bt[2], bt[3]);
        float g = giou_xy(a, b);
        atomicAdd(&s_acc[0], (double)l1);
        atomicAdd(&s_acc[1], (double)g);
    }

    // ---- ID cross-entropy: each warp handles ~3-4 rows of K=512 ----
    double id_part = 0.0;
    for (int t = wid; t < MTGT; t += NWARPS) {
        const int idx = s_match[t];
        const float* row = il + (size_t)(f * NPRED + idx) * KID;
        float xv[16];
        float mx = -FLT_MAX;
        #pragma unroll
        for (int k = 0; k < 16; k++) {
            xv[k] = row[lane + 32 * k];
            mx = fmaxf(mx, xv[k]);
        }
        #pragma unroll
        for (int off = 16; off > 0; off >>= 1)
            mx = fmaxf(mx, __shfl_xor_sync(0xffffffffu, mx, off));
        float se = 0.f;
        #pragma unroll
        for (int k = 0; k < 16; k++) se += __expf(xv[k] - mx);
        #pragma unroll
        for (int off = 16; off > 0; off >>= 1)
            se += __shfl_xor_sync(0xffffffffu, se, off);
        if (lane == 0) {
            float lse = logf(se) + mx;
            int tg = tids[f * MTGT + t];
            id_part += (double)(lse - row[tg]);
        }
    }
    if (lane == 0 && id_part != 0.0) atomicAdd(&s_acc[2], id_part);
    __syncthreads();

    // ---- publish partials; last block finalizes (threadfence reduction) ----
    if (tid == 0) {
        g_part[f * 3 + 0] = s_acc[0];
        g_part[f * 3 + 1] = s_acc[1];
        g_part[f * 3 + 2] = s_acc[2];
        __threadfence();
        unsigned t = atomicAdd(&g_done, 1u);
        s_islast = (t == F_FRAMES - 1) ? 1 : 0;
    }
    __syncthreads();

    if (s_islast) {
        __threadfence();
        double a0 = 0.0, a1 = 0.0, a2 = 0.0;
        if (tid < F_FRAMES) {
            a0 = g_part[tid * 3 + 0];
            a1 = g_part[tid * 3 + 1];
            a2 = g_part[tid * 3 + 2];
        }
        #pragma unroll
        for (int off = 16; off > 0; off >>= 1) {
            a0 += __shfl_down_sync(0xffffffffu, a0, off);
            a1 += __shfl_down_sync(0xffffffffu, a1, off);
            a2 += __shfl_down_sync(0xffffffffu, a2, off);
        }
        __shared__ double s0[4], s1[4], s2[4];
        if (lane == 0 && wid < 4) { s0[wid] = a0; s1[wid] = a1; s2[wid] = a2; }
        __syncthreads();
        if (tid == 0) {
            double t0 = s0[0] + s0[1] + s0[2] + s0[3];
            double t1 = s1[0] + s1[1] + s1[2] + s1[3];
            double t2 = s2[0] + s2[1] + s2[2] + s2[3];
            const double FM = (double)(F_FRAMES * MTGT);
            double l1   = t0 / (FM * 4.0);
            double giou = 1.0 - t1 / FM;
            double idl  = t2 / FM;
            double loss = 5.0 * l1 + 2.0 * giou + 1.0 * idl;
            out[0] = (float)loss;
            out[1] = 0.0f;
            out[2] = (float)l1;
            out[3] = (float)giou;
            out[4] = (float)idl;
            __threadfence();
            g_done = 0;      // self-reset for next graph replay
        }
    }
}

extern "C" void kernel_launch(void* const* d_in, const int* in_sizes, int n_in,
                              void* d_out, int out_size) {
    const float* pred_logits   = (const float*)d_in[0];  // [8,16,300,2]
    const float* pred_boxes    = (const float*)d_in[1];  // [8,16,300,4]
    const float* id_logits     = (const float*)d_in[2];  // [8,16,300,512]
    const int*   target_labels = (const int*)  d_in[3];  // [128,32]
    const float* target_boxes  = (const float*)d_in[4];  // [128,32,4]
    const int*   target_ids    = (const int*)  d_in[5];  // [128,32]
    float* out = (float*)d_out;

    motip_kernel<<<F_FRAMES, HTHREADS>>>(pred_logits, pred_boxes, id_logits,
                                         target_labels, target_boxes, target_ids,
                                         out);
}

// round 11
// speedup vs baseline: 3.5483x; 1.1560x over previous
#include <cuda_runtime.h>
#include <math.h>
#include <float.h>

#define F_FRAMES 128
#define NPRED    300
#define MTGT     32
#define NCLS     2
#define KID      512

#define HTHREADS 320
#define NWARPS   (HTHREADS/32)

__device__ double   g_part[F_FRAMES * 3];  // per-frame [l1_sum, giou_sum, nll_sum]
__device__ unsigned g_done = 0;            // self-resetting completion counter

struct XY { float x1, y1, x2, y2, area; };

__device__ __forceinline__ XY to_xyxy(float cx, float cy, float w, float h) {
    XY r;
    r.x1 = cx - 0.5f * w; r.y1 = cy - 0.5f * h;
    r.x2 = cx + 0.5f * w; r.y2 = cy + 0.5f * h;
    r.area = (r.x2 - r.x1) * (r.y2 - r.y1);
    return r;
}

__device__ __forceinline__ float giou_xy(const XY& a, const XY& b) {
    float ltx = fmaxf(a.x1, b.x1), lty = fmaxf(a.y1, b.y1);
    float rbx = fminf(a.x2, b.x2), rby = fminf(a.y2, b.y2);
    float w = fmaxf(rbx - ltx, 0.f), h = fmaxf(rby - lty, 0.f);
    float inter = w * h;
    float uni = a.area + b.area - inter;
    float iou = inter / uni;
    float LTx = fminf(a.x1, b.x1), LTy = fminf(a.y1, b.y1);
    float RBx = fmaxf(a.x2, b.x2), RBy = fmaxf(a.y2, b.y2);
    float W = fmaxf(RBx - LTx, 0.f), H = fmaxf(RBy - LTy, 0.f);
    float ac = W * H;
    return iou - (ac - uni) / ac;
}

// order-preserving float -> u32 (smaller float => smaller key)
__device__ __forceinline__ unsigned f2key(float f) {
    unsigned b = __float_as_uint(f);
    return (b & 0x80000000u) ? ~b : (b | 0x80000000u);
}
__device__ __forceinline__ float key2f(unsigned k) {
    unsigned b = (k & 0x80000000u) ? (k ^ 0x80000000u) : ~k;
    return __uint_as_float(b);
}

__global__ __launch_bounds__(HTHREADS, 1)
void motip_kernel(const float* __restrict__ pl,   // [F,N,2]
                  const float* __restrict__ pb,   // [F,N,4]
                  const float* __restrict__ il,   // [F,N,512]
                  const int*   __restrict__ tlab, // [F,M]
                  const float* __restrict__ tbx,  // [F,M,4]
                  const int*   __restrict__ tids, // [F,M]
                  float* __restrict__ out)        // [5]
{
    const int f    = blockIdx.x;
    const int tid  = threadIdx.x;
    const int lane = tid & 31;
    const int wid  = tid >> 5;

    __shared__ float  s_cost[MTGT * NPRED];   // [t][j]
    __shared__ float  s_u[MTGT + 1];
    __shared__ int    s_way[NPRED + 1];
    __shared__ int    s_p[NPRED + 1];
    __shared__ XY     s_tb[MTGT];
    __shared__ int    s_tl[MTGT];
    __shared__ unsigned long long s_wmin[2][NWARPS];  // parity double-buffer
    __shared__ unsigned long long s_rowkey[MTGT];
    __shared__ int    s_freelist[MTGT];
    __shared__ int    s_nfree;
    __shared__ int    s_match[MTGT];
    __shared__ double s_acc[3];
    __shared__ int    s_islast;

    // ---- init + load targets ----
    if (tid < MTGT) {
        const float* t = tbx + (size_t)(f * MTGT + tid) * 4;
        s_tb[tid] = to_xyxy(t[0], t[1], t[2], t[3]);
        s_tl[tid] = tlab[f * MTGT + tid];
    }
    if (tid <= NPRED) s_p[tid] = 0;
    if (tid < 3)      s_acc[tid] = 0.0;
    __syncthreads();

    // ---- cost build: thread j handles pred j ----
    if (tid < NPRED) {
        const float* lg = pl + (size_t)(f * NPRED + tid) * NCLS;
        float x0 = lg[0], x1 = lg[1];
        float mx = fmaxf(x0, x1);
        float e0 = expf(x0 - mx), e1 = expf(x1 - mx);
        float inv = 1.0f / (e0 + e1);
        float prob[2] = { e0 * inv, e1 * inv };

        const float* bp = pb + (size_t)(f * NPRED + tid) * 4;
        float cx = bp[0], cy = bp[1], bw = bp[2], bh = bp[3];
        XY a = to_xyxy(cx, cy, bw, bh);

        #pragma unroll 4
        for (int t = 0; t < MTGT; t++) {
            const float* tb4 = tbx + (size_t)(f * MTGT + t) * 4;
            float l1 = fabsf(cx - tb4[0]) + fabsf(cy - tb4[1])
                     + fabsf(bw - tb4[2]) + fabsf(bh - tb4[3]);
            float g  = giou_xy(a, s_tb[t]);
            float cc = -prob[s_tl[t]];
            s_cost[t * NPRED + tid] = 2.0f * cc + 5.0f * l1 + 2.0f * (-g);
        }
    }
    __syncthreads();

    // ---- row minima: warp w handles rows w, w+10, ... ----
    for (int r = wid; r < MTGT; r += NWARPS) {
        unsigned long long best = 0xFFFFFFFFFFFFFFFFULL;
        #pragma unroll
        for (int k = 0; k < 10; k++) {
            int j = lane + 32 * k;
            if (j < NPRED) {
                unsigned long long key =
                    ((unsigned long long)f2key(s_cost[r * NPRED + j]) << 32)
                    | (unsigned)j;
                best = min(best, key);
            }
        }
        #pragma unroll
        for (int off = 16; off > 0; off >>= 1)
            best = min(best, __shfl_xor_sync(0xffffffffu, best, off));
        if (lane == 0) s_rowkey[r] = best;
    }
    __syncthreads();

    // ---- greedy tight assignment + dual init (tid 0, serial over 32 rows) ----
    if (tid == 0) {
        int nf = 0;
        s_u[0] = 0.0f;
        for (int r = 0; r < MTGT; r++) {
            unsigned long long key = s_rowkey[r];
            int   jmin = (int)(key & 0xFFFFFFFFULL);
            float vmin = key2f((unsigned)(key >> 32));
            s_u[r + 1] = vmin;                    // u[i] = exact row min, v = 0
            if (s_p[jmin + 1] == 0) s_p[jmin + 1] = r + 1;   // tight edge, free col
            else                    s_freelist[nf++] = r + 1;
        }
        s_nfree = nf;
    }
    __syncthreads();

    // ---- JV augmentation for conflicted rows only (fp32, 1 barrier/iter) ----
    const int  jcol   = tid + 1;
    const bool active = (tid < NPRED);
    float v = 0.0f;                        // v[jcol] in register (greedy leaves v=0)
    const int nfree = s_nfree;

    for (int fi = 0; fi < nfree; fi++) {
        const int i = s_freelist[fi];
        float mv    = FLT_MAX;
        bool  used  = false;
        if (tid == 0) s_p[0] = i;
        int j0  = 0;
        int par = 0;
        __syncthreads();   // phase start: s_p[0] + previous augment visible

        while (true) {
            // -- compute: scan own column against current row i0 --
            const int   i0   = s_p[j0];         // row of unused col (or free row)
            const float u_i0 = s_u[i0];         // stable during this path

            unsigned long long bk = 0xFFFFFFFFFFFFFFFFULL;
            if (active && !used) {
                float cur = s_cost[(i0 - 1) * NPRED + tid] - u_i0 - v;
                if (cur < mv) { mv = cur; s_way[jcol] = j0; }
                bk = ((unsigned long long)f2key(mv) << 32)
                   | (unsigned long long)jcol;
            }
            #pragma unroll
            for (int off = 16; off > 0; off >>= 1)
                bk = min(bk, __shfl_xor_sync(0xffffffffu, bk, off));
            if (lane == 0) s_wmin[par][wid] = bk;
            __syncthreads();   // the ONE barrier

            // -- select: every thread reduces the 10 warp minima --
            unsigned long long kk = s_wmin[par][0];
            #pragma unroll
            for (int w = 1; w < NWARPS; w++)
                kk = min(kk, s_wmin[par][w]);
            const int   j1    = (int)(kk & 0xFFFFFFFFULL);
            const float delta = key2f((unsigned)(kk >> 32));  // == owner's mv
            const int   pj1   = s_p[j1];

            // -- update (no shared deps for next compute; see dependency audit) --
            if (tid == 0) s_u[s_p[0]] += delta;           // free row (virtual col 0)
            if (active) {
                if (used) {
                    v -= delta;
                    s_u[s_p[jcol]] += delta;              // distinct rows, no conflict
                } else {
                    mv -= delta;
                    if (jcol == j1) used = true;
                }
            }

            par ^= 1;
            j0 = j1;
            if (pj1 == 0) break;
        }

        // augment (scalar); visibility covered by next phase-start barrier
        if (tid == 0) {
            int jj = j0;
            while (jj) {
                int jn = s_way[jj];
                s_p[jj] = s_p[jn];
                jj = jn;
            }
        }
    }
    __syncthreads();

    // ---- emit matches to smem ----
    if (active) {
        const int r = s_p[jcol];
        if (r > 0) s_match[r - 1] = jcol - 1;
    }
    __syncthreads();

    // ---- L1 + pair GIoU: one thread per target ----
    if (tid < MTGT) {
        const int idx = s_match[tid];
        const float* bp2 = pb  + (size_t)(f * NPRED + idx) * 4;
        const float* bt  = tbx + (size_t)(f * MTGT + tid) * 4;
        float l1 = fabsf(bp2[0] - bt[0]) + fabsf(bp2[1] - bt[1])
                 + fabsf(bp2[2] - bt[2]) + fabsf(bp2[3] - bt[3]);
        XY a = to_xyxy(bp2[0], bp2[1], bp2[2], bp2[3]);
        XY b = to_xyxy(bt[0], bt[1], bt[2], bt[3]);
        float g = giou_xy(a, b);
        atomicAdd(&s_acc[0], (double)l1);
        atomicAdd(&s_acc[1], (double)g);
    }

    // ---- ID cross-entropy: each warp handles ~3-4 rows of K=512 ----
    double id_part = 0.0;
    for (int t = wid; t < MTGT; t += NWARPS) {
        const int idx = s_match[t];
        const float* row = il + (size_t)(f * NPRED + idx) * KID;
        float xv[16];
        float mx = -FLT_MAX;
        #pragma unroll
        for (int k = 0; k < 16; k++) {
            xv[k] = row[lane + 32 * k];
            mx = fmaxf(mx, xv[k]);
        }
        #pragma unroll
        for (int off = 16; off > 0; off >>= 1)
            mx = fmaxf(mx, __shfl_xor_sync(0xffffffffu, mx, off));
        float se = 0.f;
        #pragma unroll
        for (int k = 0; k < 16; k++) se += __expf(xv[k] - mx);
        #pragma unroll
        for (int off = 16; off > 0; off >>= 1)
            se += __shfl_xor_sync(0xffffffffu, se, off);
        if (lane == 0) {
            float lse = logf(se) + mx;
            int tg = tids[f * MTGT + t];
            id_part += (double)(lse - row[tg]);
        }
    }
    if (lane == 0 && id_part != 0.0) atomicAdd(&s_acc[2], id_part);
    __syncthreads();

    // ---- publish partials; last block finalizes ----
    if (tid == 0) {
        g_part[f * 3 + 0] = s_acc[0];
        g_part[f * 3 + 1] = s_acc[1];
        g_part[f * 3 + 2] = s_acc[2];
        __threadfence();
        unsigned t = atomicAdd(&g_done, 1u);
        s_islast = (t == F_FRAMES - 1) ? 1 : 0;
    }
    __syncthreads();

    if (s_islast) {
        __threadfence();
        double a0 = 0.0, a1 = 0.0, a2 = 0.0;
        if (tid < F_FRAMES) {
            a0 = g_part[tid * 3 + 0];
            a1 = g_part[tid * 3 + 1];
            a2 = g_part[tid * 3 + 2];
        }
        #pragma unroll
        for (int off = 16; off > 0; off >>= 1) {
            a0 += __shfl_down_sync(0xffffffffu, a0, off);
            a1 += __shfl_down_sync(0xffffffffu, a1, off);
            a2 += __shfl_down_sync(0xffffffffu, a2, off);
        }
        __shared__ double s0[4], s1[4], s2[4];
        if (lane == 0 && wid < 4) { s0[wid] = a0; s1[wid] = a1; s2[wid] = a2; }
        __syncthreads();
        if (tid == 0) {
            double t0 = s0[0] + s0[1] + s0[2] + s0[3];
            double t1 = s1[0] + s1[1] + s1[2] + s1[3];
            double t2 = s2[0] + s2[1] + s2[2] + s2[3];
            const double FM = (double)(F_FRAMES * MTGT);
            double l1   = t0 / (FM * 4.0);
            double giou = 1.0 - t1 / FM;
            double idl  = t2 / FM;
            double loss = 5.0 * l1 + 2.0 * giou + 1.0 * idl;
            out[0] = (float)loss;
            out[1] = 0.0f;
            out[2] = (float)l1;
            out[3] = (float)giou;
            out[4] = (float)idl;
            __threadfence();
            g_done = 0;      // self-reset for next graph replay
        }
    }
}

extern "C" void kernel_launch(void* const* d_in, const int* in_sizes, int n_in,
                              void* d_out, int out_size) {
    const float* pred_logits   = (const float*)d_in[0];  // [8,16,300,2]
    const float* pred_boxes    = (const float*)d_in[1];  // [8,16,300,4]
    const float* id_logits     = (const float*)d_in[2];  // [8,16,300,512]
    const int*   target_labels = (const int*)  d_in[3];  // [128,32]
    const float* target_boxes  = (const float*)d_in[4];  // [128,32,4]
    const int*   target_ids    = (const int*)  d_in[5];  // [128,32]
    float* out = (float*)d_out;

    motip_kernel<<<F_FRAMES, HTHREADS>>>(pred_logits, pred_boxes, id_logits,
                                         target_labels, target_boxes, target_ids,
                                         out);
}

// round 12
// speedup vs baseline: 3.7429x; 1.0548x over previous
#include <cuda_runtime.h>
#include <math.h>
#include <float.h>

#define F_FRAMES 128
#define NPRED    300
#define MTGT     32
#define NCLS     2
#define KID      512

#define HTHREADS 320
#define NWARPS   (HTHREADS/32)

__device__ double   g_part[F_FRAMES * 3];  // per-frame [l1_sum, giou_sum, nll_sum]
__device__ unsigned g_done = 0;            // self-resetting completion counter

struct XY { float x1, y1, x2, y2, area; };

__device__ __forceinline__ XY to_xyxy(float cx, float cy, float w, float h) {
    XY r;
    r.x1 = cx - 0.5f * w; r.y1 = cy - 0.5f * h;
    r.x2 = cx + 0.5f * w; r.y2 = cy + 0.5f * h;
    r.area = (r.x2 - r.x1) * (r.y2 - r.y1);
    return r;
}

__device__ __forceinline__ float giou_xy(const XY& a, const XY& b) {
    float ltx = fmaxf(a.x1, b.x1), lty = fmaxf(a.y1, b.y1);
    float rbx = fminf(a.x2, b.x2), rby = fminf(a.y2, b.y2);
    float w = fmaxf(rbx - ltx, 0.f), h = fmaxf(rby - lty, 0.f);
    float inter = w * h;
    float uni = a.area + b.area - inter;
    float iou = inter / uni;
    float LTx = fminf(a.x1, b.x1), LTy = fminf(a.y1, b.y1);
    float RBx = fmaxf(a.x2, b.x2), RBy = fmaxf(a.y2, b.y2);
    float W = fmaxf(RBx - LTx, 0.f), H = fmaxf(RBy - LTy, 0.f);
    float ac = W * H;
    return iou - (ac - uni) / ac;
}

// order-preserving float -> u32 (smaller float => smaller key)
__device__ __forceinline__ unsigned f2key(float f) {
    unsigned b = __float_as_uint(f);
    return (b & 0x80000000u) ? ~b : (b | 0x80000000u);
}
__device__ __forceinline__ float key2f(unsigned k) {
    unsigned b = (k & 0x80000000u) ? (k ^ 0x80000000u) : ~k;
    return __uint_as_float(b);
}

__global__ __launch_bounds__(HTHREADS, 1)
void motip_kernel(const float* __restrict__ pl,   // [F,N,2]
                  const float* __restrict__ pb,   // [F,N,4]
                  const float* __restrict__ il,   // [F,N,512]
                  const int*   __restrict__ tlab, // [F,M]
                  const float* __restrict__ tbx,  // [F,M,4]
                  const int*   __restrict__ tids, // [F,M]
                  float* __restrict__ out)        // [5]
{
    const int f    = blockIdx.x;
    const int tid  = threadIdx.x;
    const int lane = tid & 31;
    const int wid  = tid >> 5;

    __shared__ float  s_cost[MTGT * NPRED];   // [t][j]
    __shared__ float  s_u[MTGT + 1];
    __shared__ int    s_way[NPRED + 1];
    __shared__ int    s_p[NPRED + 1];
    __shared__ XY     s_tb[MTGT];
    __shared__ int    s_tl[MTGT];
    __shared__ unsigned long long s_wmin[2][NWARPS];  // parity double-buffer
    __shared__ unsigned long long s_rowkey[MTGT];
    __shared__ int    s_freelist[MTGT];
    __shared__ int    s_nfree;
    __shared__ int    s_match[MTGT];
    __shared__ double s_acc[3];
    __shared__ int    s_islast;

    // ---- init + load targets ----
    if (tid < MTGT) {
        const float* t = tbx + (size_t)(f * MTGT + tid) * 4;
        s_tb[tid] = to_xyxy(t[0], t[1], t[2], t[3]);
        s_tl[tid] = tlab[f * MTGT + tid];
    }
    if (tid <= NPRED) s_p[tid] = 0;
    if (tid < 3)      s_acc[tid] = 0.0;
    __syncthreads();

    // ---- cost build: thread j handles pred j ----
    if (tid < NPRED) {
        const float* lg = pl + (size_t)(f * NPRED + tid) * NCLS;
        float x0 = lg[0], x1 = lg[1];
        float mx = fmaxf(x0, x1);
        float e0 = expf(x0 - mx), e1 = expf(x1 - mx);
        float inv = 1.0f / (e0 + e1);
        float prob[2] = { e0 * inv, e1 * inv };

        const float* bp = pb + (size_t)(f * NPRED + tid) * 4;
        float cx = bp[0], cy = bp[1], bw = bp[2], bh = bp[3];
        XY a = to_xyxy(cx, cy, bw, bh);

        #pragma unroll 4
        for (int t = 0; t < MTGT; t++) {
            const float* tb4 = tbx + (size_t)(f * MTGT + t) * 4;
            float l1 = fabsf(cx - tb4[0]) + fabsf(cy - tb4[1])
                     + fabsf(bw - tb4[2]) + fabsf(bh - tb4[3]);
            float g  = giou_xy(a, s_tb[t]);
            float cc = -prob[s_tl[t]];
            s_cost[t * NPRED + tid] = 2.0f * cc + 5.0f * l1 + 2.0f * (-g);
        }
    }
    __syncthreads();

    // ---- row minima: warp w handles rows w, w+10, ... ----
    for (int r = wid; r < MTGT; r += NWARPS) {
        unsigned long long best = 0xFFFFFFFFFFFFFFFFULL;
        #pragma unroll
        for (int k = 0; k < 10; k++) {
            int j = lane + 32 * k;
            if (j < NPRED) {
                unsigned long long key =
                    ((unsigned long long)f2key(s_cost[r * NPRED + j]) << 32)
                    | (unsigned)j;
                best = min(best, key);
            }
        }
        #pragma unroll
        for (int off = 16; off > 0; off >>= 1)
            best = min(best, __shfl_xor_sync(0xffffffffu, best, off));
        if (lane == 0) s_rowkey[r] = best;
    }
    __syncthreads();

    // ---- greedy tight assignment + dual init (tid 0, serial over 32 rows) ----
    if (tid == 0) {
        int nf = 0;
        s_u[0] = 0.0f;
        for (int r = 0; r < MTGT; r++) {
            unsigned long long key = s_rowkey[r];
            int   jmin = (int)(key & 0xFFFFFFFFULL);
            float vmin = key2f((unsigned)(key >> 32));
            s_u[r + 1] = vmin;                    // u[i] = exact row min, v = 0
            if (s_p[jmin + 1] == 0) s_p[jmin + 1] = r + 1;   // tight edge, free col
            else                    s_freelist[nf++] = r + 1;
        }
        s_nfree = nf;
    }
    __syncthreads();

    // ---- JV augmentation for conflicted rows only (fp32, 1 barrier/iter,
    //      REDUX.min warp argmin) ----
    const int  jcol   = tid + 1;
    const bool active = (tid < NPRED);
    float v = 0.0f;                        // v[jcol] in register (greedy leaves v=0)
    const int nfree = s_nfree;

    for (int fi = 0; fi < nfree; fi++) {
        const int i = s_freelist[fi];
        float mv    = FLT_MAX;
        bool  used  = false;
        if (tid == 0) s_p[0] = i;
        int j0  = 0;
        int par = 0;
        __syncthreads();   // phase start: s_p[0] + previous augment visible

        while (true) {
            // -- compute: scan own column against current row i0 --
            const int   i0   = s_p[j0];
            const float u_i0 = s_u[i0];

            unsigned vkey = 0xFFFFFFFFu;
            if (active && !used) {
                float cur = s_cost[(i0 - 1) * NPRED + tid] - u_i0 - v;
                if (cur < mv) { mv = cur; s_way[jcol] = j0; }
                vkey = f2key(mv);
            }
            // single-instruction warp min (value), then lowest-index tie-break
            unsigned vmin = __reduce_min_sync(0xffffffffu, vkey);
            unsigned jc   = (vkey == vmin) ? (unsigned)jcol : 0xFFFFFFFFu;
            unsigned jmin = __reduce_min_sync(0xffffffffu, jc);
            if (lane == 0)
                s_wmin[par][wid] = ((unsigned long long)vmin << 32) | jmin;
            __syncthreads();   // the ONE barrier

            // -- select: every thread reduces the 10 warp minima --
            unsigned long long kk = s_wmin[par][0];
            #pragma unroll
            for (int w = 1; w < NWARPS; w++)
                kk = min(kk, s_wmin[par][w]);
            const int   j1    = (int)(kk & 0xFFFFFFFFULL);
            const float delta = key2f((unsigned)(kk >> 32));  // == owner's mv, exact
            const int   pj1   = s_p[j1];

            // -- update (no shared deps for next compute phase) --
            if (tid == 0) s_u[s_p[0]] += delta;           // free row (virtual col 0)
            if (active) {
                if (used) {
                    v -= delta;
                    s_u[s_p[jcol]] += delta;              // distinct rows, no conflict
                } else {
                    mv -= delta;
                    if (jcol == j1) used = true;
                }
            }

            par ^= 1;
            j0 = j1;
            if (pj1 == 0) break;
        }

        // augment (scalar); visibility covered by next phase-start barrier
        if (tid == 0) {
            int jj = j0;
            while (jj) {
                int jn = s_way[jj];
                s_p[jj] = s_p[jn];
                jj = jn;
            }
        }
    }
    __syncthreads();

    // ---- emit matches to smem ----
    if (active) {
        const int r = s_p[jcol];
        if (r > 0) s_match[r - 1] = jcol - 1;
    }
    __syncthreads();

    // ---- L1 + pair GIoU: one thread per target ----
    if (tid < MTGT) {
        const int idx = s_match[tid];
        const float* bp2 = pb  + (size_t)(f * NPRED + idx) * 4;
        const float* bt  = tbx + (size_t)(f * MTGT + tid) * 4;
        float l1 = fabsf(bp2[0] - bt[0]) + fabsf(bp2[1] - bt[1])
                 + fabsf(bp2[2] - bt[2]) + fabsf(bp2[3] - bt[3]);
        XY a = to_xyxy(bp2[0], bp2[1], bp2[2], bp2[3]);
        XY b = to_xyxy(bt[0], bt[1], bt[2], bt[3]);
        float g = giou_xy(a, b);
        atomicAdd(&s_acc[0], (double)l1);
        atomicAdd(&s_acc[1], (double)g);
    }

    // ---- ID cross-entropy: each warp handles ~3-4 rows of K=512 ----
    double id_part = 0.0;
    for (int t = wid; t < MTGT; t += NWARPS) {
        const int idx = s_match[t];
        const float* row = il + (size_t)(f * NPRED + idx) * KID;
        float xv[16];
        float mx = -FLT_MAX;
        #pragma unroll
        for (int k = 0; k < 16; k++) {
            xv[k] = row[lane + 32 * k];
            mx = fmaxf(mx, xv[k]);
        }
        #pragma unroll
        for (int off = 16; off > 0; off >>= 1)
            mx = fmaxf(mx, __shfl_xor_sync(0xffffffffu, mx, off));
        float se = 0.f;
        #pragma unroll
        for (int k = 0; k < 16; k++) se += __expf(xv[k] - mx);
        #pragma unroll
        for (int off = 16; off > 0; off >>= 1)
            se += __shfl_xor_sync(0xffffffffu, se, off);
        if (lane == 0) {
            float lse = logf(se) + mx;
            int tg = tids[f * MTGT + t];
            id_part += (double)(lse - row[tg]);
        }
    }
    if (lane == 0 && id_part != 0.0) atomicAdd(&s_acc[2], id_part);
    __syncthreads();

    // ---- publish partials; last block finalizes ----
    if (tid == 0) {
        g_part[f * 3 + 0] = s_acc[0];
        g_part[f * 3 + 1] = s_acc[1];
        g_part[f * 3 + 2] = s_acc[2];
        __threadfence();
        unsigned t = atomicAdd(&g_done, 1u);
        s_islast = (t == F_FRAMES - 1) ? 1 : 0;
    }
    __syncthreads();

    if (s_islast) {
        __threadfence();
        double a0 = 0.0, a1 = 0.0, a2 = 0.0;
        if (tid < F_FRAMES) {
            a0 = g_part[tid * 3 + 0];
            a1 = g_part[tid * 3 + 1];
            a2 = g_part[tid * 3 + 2];
        }
        #pragma unroll
        for (int off = 16; off > 0; off >>= 1) {
            a0 += __shfl_down_sync(0xffffffffu, a0, off);
            a1 += __shfl_down_sync(0xffffffffu, a1, off);
            a2 += __shfl_down_sync(0xffffffffu, a2, off);
        }
        __shared__ double s0[4], s1[4], s2[4];
        if (lane == 0 && wid < 4) { s0[wid] = a0; s1[wid] = a1; s2[wid] = a2; }
        __syncthreads();
        if (tid == 0) {
            double t0 = s0[0] + s0[1] + s0[2] + s0[3];
            double t1 = s1[0] + s1[1] + s1[2] + s1[3];
            double t2 = s2[0] + s2[1] + s2[2] + s2[3];
            const double FM = (double)(F_FRAMES * MTGT);
            double l1   = t0 / (FM * 4.0);
            double giou = 1.0 - t1 / FM;
            double idl  = t2 / FM;
            double loss = 5.0 * l1 + 2.0 * giou + 1.0 * idl;
            out[0] = (float)loss;
            out[1] = 0.0f;
            out[2] = (float)l1;
            out[3] = (float)giou;
            out[4] = (float)idl;
            __threadfence();
            g_done = 0;      // self-reset for next graph replay
        }
    }
}

extern "C" void kernel_launch(void* const* d_in, const int* in_sizes, int n_in,
                              void* d_out, int out_size) {
    const float* pred_logits   = (const float*)d_in[0];  // [8,16,300,2]
    const float* pred_boxes    = (const float*)d_in[1];  // [8,16,300,4]
    const float* id_logits     = (const float*)d_in[2];  // [8,16,300,512]
    const int*   target_labels = (const int*)  d_in[3];  // [128,32]
    const float* target_boxes  = (const float*)d_in[4];  // [128,32,4]
    const int*   target_ids    = (const int*)  d_in[5];  // [128,32]
    float* out = (float*)d_out;

    motip_kernel<<<F_FRAMES, HTHREADS>>>(pred_logits, pred_boxes, id_logits,
                                         target_labels, target_boxes, target_ids,
                                         out);
}